// round 4
// baseline (speedup 1.0000x reference)
#include <cuda_runtime.h>
#include <cuda_bf16.h>

#define NN 50000
#define NE 800000
#define NG 256
#define F  64

// ---------------- scratch ----------------
__device__ __align__(16) float g_h[NN * F];     // h * dinv[src] (pre-scaled)
__device__ __align__(16) float g_agg[NN * F];   // self-loop init, then full agg
__device__ __align__(16) float g_sums[NG * F];
__device__ float g_cnt[NG];
__device__ float g_dinv[NN];
__device__ float g_invdeg[NN];
__device__ int   g_deg[NN];
__device__ int   g_rowstart[NN];
__device__ int   g_cursor[NN];
__device__ int   g_counter;
__device__ int   g_ssorted[NE];

__device__ __forceinline__ void red_add_v4(float* p, float4 v) {
    asm volatile("red.global.add.v4.f32 [%0], {%1, %2, %3, %4};"
                 :: "l"(p), "f"(v.x), "f"(v.y), "f"(v.z), "f"(v.w) : "memory");
}

// ---------------- prep kernels ----------------
__global__ void zero_kernel() {
    int i = blockIdx.x * blockDim.x + threadIdx.x;
    if (i < NN) g_deg[i] = 0;
    if (i < NG * F) g_sums[i] = 0.0f;
    if (i < NG) g_cnt[i] = 0.0f;
    if (i == 0) g_counter = 0;
}

__global__ void deg_kernel(const int* __restrict__ dst) {
    int e = blockIdx.x * blockDim.x + threadIdx.x;
    if (e < NE) atomicAdd(&g_deg[dst[e]], 1);
}

// dinv + row-range assignment (order-free: any disjoint ranges are valid CSR)
__global__ void dinv_kernel(const int* __restrict__ batch) {
    int i = blockIdx.x * blockDim.x + threadIdx.x;
    if (i < NN) {
        int n = g_deg[i];
        float d = (float)(n + 1);
        g_dinv[i] = rsqrtf(d);
        g_invdeg[i] = 1.0f / d;
        int rs = atomicAdd(&g_counter, n);
        g_rowstart[i] = rs;
        g_cursor[i] = rs;
        atomicAdd(&g_cnt[batch[i]], 1.0f);
    }
}

__global__ void scatter_kernel(const int* __restrict__ src, const int* __restrict__ dst) {
    int e = blockIdx.x * blockDim.x + threadIdx.x;
    if (e < NE) {
        int d = dst[e];
        int pos = atomicAdd(&g_cursor[d], 1);
        g_ssorted[pos] = src[e];
    }
}

// ---------------- GEMM + self-loop init ----------------
// in = (FIRST ? x : relu(g_agg + b_prev)); a = in @ W
// g_h = a * dinv; g_agg = a * invdeg
// Block: 128 threads = 32 groups x 4 parts; group covers 2 nodes; 64 nodes/block.
template <bool FIRST>
__global__ __launch_bounds__(128) void gemm_kernel(const float* __restrict__ x,
                                                   const float* __restrict__ W,
                                                   const float* __restrict__ bprev) {
    __shared__ float4 Ws[F * 16];
    int tid = threadIdx.x;
    const float4* W4 = (const float4*)W;
#pragma unroll
    for (int i = tid; i < F * 16; i += 128) Ws[i] = W4[i];
    __syncthreads();

    int part = tid & 3;
    int grp = tid >> 2;                       // 0..31
    int base = blockIdx.x * 64 + grp * 2;

    const float4* in4 = FIRST ? (const float4*)x : (const float4*)g_agg;
    const float4* b4 = (const float4*)bprev;

    float4 acc[2][4];
#pragma unroll
    for (int r = 0; r < 2; ++r)
#pragma unroll
        for (int j = 0; j < 4; ++j) acc[r][j] = make_float4(0.f, 0.f, 0.f, 0.f);

    bool ok0 = (base < NN);
    bool ok1 = (base + 1 < NN);

#pragma unroll
    for (int k4 = 0; k4 < 16; ++k4) {
        float4 bv;
        if (!FIRST) bv = b4[k4];
        float xs[2][4];
#pragma unroll
        for (int r = 0; r < 2; ++r) {
            bool ok = r ? ok1 : ok0;
            float4 xv = make_float4(0.f, 0.f, 0.f, 0.f);
            if (ok) {
                xv = in4[(size_t)(base + r) * 16 + k4];
                if (!FIRST) {
                    xv.x = fmaxf(xv.x + bv.x, 0.f);
                    xv.y = fmaxf(xv.y + bv.y, 0.f);
                    xv.z = fmaxf(xv.z + bv.z, 0.f);
                    xv.w = fmaxf(xv.w + bv.w, 0.f);
                }
            }
            xs[r][0] = xv.x; xs[r][1] = xv.y; xs[r][2] = xv.z; xs[r][3] = xv.w;
        }
#pragma unroll
        for (int kk = 0; kk < 4; ++kk) {
            const float4* wrow = &Ws[(k4 * 4 + kk) * 16 + part * 4];
            float4 w0 = wrow[0], w1 = wrow[1], w2 = wrow[2], w3 = wrow[3];
#pragma unroll
            for (int r = 0; r < 2; ++r) {
                float v = xs[r][kk];
                acc[r][0].x = fmaf(v, w0.x, acc[r][0].x);
                acc[r][0].y = fmaf(v, w0.y, acc[r][0].y);
                acc[r][0].z = fmaf(v, w0.z, acc[r][0].z);
                acc[r][0].w = fmaf(v, w0.w, acc[r][0].w);
                acc[r][1].x = fmaf(v, w1.x, acc[r][1].x);
                acc[r][1].y = fmaf(v, w1.y, acc[r][1].y);
                acc[r][1].z = fmaf(v, w1.z, acc[r][1].z);
                acc[r][1].w = fmaf(v, w1.w, acc[r][1].w);
                acc[r][2].x = fmaf(v, w2.x, acc[r][2].x);
                acc[r][2].y = fmaf(v, w2.y, acc[r][2].y);
                acc[r][2].z = fmaf(v, w2.z, acc[r][2].z);
                acc[r][2].w = fmaf(v, w2.w, acc[r][2].w);
                acc[r][3].x = fmaf(v, w3.x, acc[r][3].x);
                acc[r][3].y = fmaf(v, w3.y, acc[r][3].y);
                acc[r][3].z = fmaf(v, w3.z, acc[r][3].z);
                acc[r][3].w = fmaf(v, w3.w, acc[r][3].w);
            }
        }
    }

#pragma unroll
    for (int r = 0; r < 2; ++r) {
        int node = base + r;
        if (node >= NN) continue;
        float dv = g_dinv[node];
        float id = g_invdeg[node];
        float4* hr = (float4*)(g_h + (size_t)node * F) + part * 4;
        float4* ar = (float4*)(g_agg + (size_t)node * F) + part * 4;
#pragma unroll
        for (int j = 0; j < 4; ++j) {
            float4 a = acc[r][j];
            hr[j] = make_float4(a.x * dv, a.y * dv, a.z * dv, a.w * dv);
            ar[j] = make_float4(a.x * id, a.y * id, a.z * id, a.w * id);
        }
    }
}

// ---------------- CSR aggregation: one 16-lane group per dst ----------------
// g_agg[d] = self_term + dinv[d] * sum_{s in row(d)} g_h[s]
// LAST: additionally pool relu(out + b3) into g_sums per graph.
template <bool LAST>
__global__ __launch_bounds__(256) void agg_kernel(const int* __restrict__ batch,
                                                  const float* __restrict__ b3) {
    int t = blockIdx.x * blockDim.x + threadIdx.x;
    int d = t >> 4;
    int l = t & 15;
    if (d >= NN) return;
    int start = g_rowstart[d];
    int n = g_deg[d];
    const float4* h4 = (const float4*)g_h;

    float4 acc = make_float4(0.f, 0.f, 0.f, 0.f);
    int i = 0;
    for (; i + 4 <= n; i += 4) {
        int s0 = g_ssorted[start + i];
        int s1 = g_ssorted[start + i + 1];
        int s2 = g_ssorted[start + i + 2];
        int s3 = g_ssorted[start + i + 3];
        float4 v0 = h4[(size_t)s0 * 16 + l];
        float4 v1 = h4[(size_t)s1 * 16 + l];
        float4 v2 = h4[(size_t)s2 * 16 + l];
        float4 v3 = h4[(size_t)s3 * 16 + l];
        acc.x += (v0.x + v1.x) + (v2.x + v3.x);
        acc.y += (v0.y + v1.y) + (v2.y + v3.y);
        acc.z += (v0.z + v1.z) + (v2.z + v3.z);
        acc.w += (v0.w + v1.w) + (v2.w + v3.w);
    }
    for (; i < n; ++i) {
        int s0 = g_ssorted[start + i];
        float4 v0 = h4[(size_t)s0 * 16 + l];
        acc.x += v0.x; acc.y += v0.y; acc.z += v0.z; acc.w += v0.w;
    }

    float dd = g_dinv[d];
    float4* ar = (float4*)g_agg + (size_t)d * 16 + l;
    float4 self = *ar;
    float4 out = make_float4(fmaf(acc.x, dd, self.x),
                             fmaf(acc.y, dd, self.y),
                             fmaf(acc.z, dd, self.z),
                             fmaf(acc.w, dd, self.w));
    if (!LAST) {
        *ar = out;
    } else {
        float4 bv = ((const float4*)b3)[l];
        out.x = fmaxf(out.x + bv.x, 0.f);
        out.y = fmaxf(out.y + bv.y, 0.f);
        out.z = fmaxf(out.z + bv.z, 0.f);
        out.w = fmaxf(out.w + bv.w, 0.f);
        int g = batch[d];
        red_add_v4(g_sums + (size_t)g * F + l * 4, out);
    }
}

// out[g] = (sums[g] . Wl) / max(cnt,1) + bl
__global__ void final_kernel(const float* __restrict__ Wl, const float* __restrict__ bl,
                             float* __restrict__ out) {
    int g = threadIdx.x;
    float c = fmaxf(g_cnt[g], 1.0f);
    float acc = 0.f;
#pragma unroll
    for (int f = 0; f < F; ++f) acc = fmaf(g_sums[g * F + f], Wl[f], acc);
    out[g] = acc / c + bl[0];
}

// ---------------- launch ----------------
extern "C" void kernel_launch(void* const* d_in, const int* in_sizes, int n_in,
                              void* d_out, int out_size) {
    const float* x   = (const float*)d_in[0];
    const int* src   = (const int*)d_in[1];
    const int* dst   = (const int*)d_in[2];
    const int* batch = (const int*)d_in[3];
    const float* W1 = (const float*)d_in[4];
    const float* b1 = (const float*)d_in[5];
    const float* W2 = (const float*)d_in[6];
    const float* b2 = (const float*)d_in[7];
    const float* W3 = (const float*)d_in[8];
    const float* b3 = (const float*)d_in[9];
    const float* Wl = (const float*)d_in[10];
    const float* bl = (const float*)d_in[11];
    float* out = (float*)d_out;

    const int NB_NODE = (NN + 255) / 256;        // 196
    const int NB_EDGE = (NE + 255) / 256;        // 3125
    const int NB_GEMM = (NN + 63) / 64;          // 782 (64 nodes per block)
    const int NB_AGG  = (NN * 16 + 255) / 256;   // 3125

    // prep: degrees, dinv, CSR build (no scan — atomic range assignment)
    zero_kernel<<<NB_NODE, 256>>>();
    deg_kernel<<<NB_EDGE, 256>>>(dst);
    dinv_kernel<<<NB_NODE, 256>>>(batch);
    scatter_kernel<<<NB_EDGE, 256>>>(src, dst);

    // layer 1
    gemm_kernel<true><<<NB_GEMM, 128>>>(x, W1, nullptr);
    agg_kernel<false><<<NB_AGG, 256>>>(batch, b3);
    // layer 2
    gemm_kernel<false><<<NB_GEMM, 128>>>(nullptr, W2, b1);
    agg_kernel<false><<<NB_AGG, 256>>>(batch, b3);
    // layer 3 (+ fused pool)
    gemm_kernel<false><<<NB_GEMM, 128>>>(nullptr, W3, b2);
    agg_kernel<true><<<NB_AGG, 256>>>(batch, b3);

    final_kernel<<<1, 256>>>(Wl, bl, out);
}

// round 5
// speedup vs baseline: 1.1437x; 1.1437x over previous
#include <cuda_runtime.h>
#include <cuda_bf16.h>

#define NN 50000
#define NE 800000
#define NG 256
#define F  64
#define NB_SCAN 196   // ceil(NN/256)

// ---------------- scratch ----------------
__device__ __align__(16) float g_h[NN * F];     // h * dinv[src] (pre-scaled)
__device__ __align__(16) float g_agg[NN * F];   // self-loop init, then full agg
__device__ __align__(16) float g_sums[NG * F];
__device__ float g_cnt[NG];
__device__ float g_dinv[NN];
__device__ float g_invdeg[NN];
__device__ int   g_deg[NN];
__device__ int   g_rowstart[NN];
__device__ int   g_cursor[NN];
__device__ int   g_bsum[NB_SCAN];
__device__ int   g_boff[NB_SCAN];
__device__ int   g_ssorted[NE];

__device__ __forceinline__ void red_add_v4(float* p, float4 v) {
    asm volatile("red.global.add.v4.f32 [%0], {%1, %2, %3, %4};"
                 :: "l"(p), "f"(v.x), "f"(v.y), "f"(v.z), "f"(v.w) : "memory");
}

// ---------------- prep kernels ----------------
__global__ void zero_kernel() {
    int i = blockIdx.x * blockDim.x + threadIdx.x;
    if (i < NN) g_deg[i] = 0;
    if (i < NG * F) g_sums[i] = 0.0f;
    if (i < NG) g_cnt[i] = 0.0f;
}

__global__ void deg_kernel(const int* __restrict__ dst) {
    int e = blockIdx.x * blockDim.x + threadIdx.x;
    if (e < NE) atomicAdd(&g_deg[dst[e]], 1);
}

__global__ void dinv_kernel(const int* __restrict__ batch) {
    int i = blockIdx.x * blockDim.x + threadIdx.x;
    if (i < NN) {
        float d = (float)(g_deg[i] + 1);
        g_dinv[i] = rsqrtf(d);
        g_invdeg[i] = 1.0f / d;
        atomicAdd(&g_cnt[batch[i]], 1.0f);
    }
}

// exclusive scan of g_deg, 3-phase (keeps rows in node order -> locality)
__global__ void scan1_kernel() {
    __shared__ int s[2][256];
    int tid = threadIdx.x;
    int i = blockIdx.x * 256 + tid;
    int v = (i < NN) ? g_deg[i] : 0;
    s[0][tid] = v;
    __syncthreads();
    int cur = 0;
#pragma unroll
    for (int off = 1; off < 256; off <<= 1) {
        int val = s[cur][tid];
        if (tid >= off) val += s[cur][tid - off];
        s[cur ^ 1][tid] = val;
        cur ^= 1;
        __syncthreads();
    }
    int excl = (tid == 0) ? 0 : s[cur][tid - 1];
    if (i < NN) g_rowstart[i] = excl;
    if (tid == 255) g_bsum[blockIdx.x] = s[cur][255];
}

__global__ void scan2_kernel() {
    __shared__ int s[2][256];
    int tid = threadIdx.x;
    s[0][tid] = (tid < NB_SCAN) ? g_bsum[tid] : 0;
    __syncthreads();
    int cur = 0;
#pragma unroll
    for (int off = 1; off < 256; off <<= 1) {
        int val = s[cur][tid];
        if (tid >= off) val += s[cur][tid - off];
        s[cur ^ 1][tid] = val;
        cur ^= 1;
        __syncthreads();
    }
    if (tid < NB_SCAN) g_boff[tid] = (tid == 0) ? 0 : s[cur][tid - 1];
}

__global__ void scan3_kernel() {
    int i = blockIdx.x * 256 + threadIdx.x;
    if (i < NN) {
        int rs = g_rowstart[i] + g_boff[blockIdx.x];
        g_rowstart[i] = rs;
        g_cursor[i] = rs;
    }
}

__global__ void scatter_kernel(const int* __restrict__ src, const int* __restrict__ dst) {
    int e = blockIdx.x * blockDim.x + threadIdx.x;
    if (e < NE) {
        int d = dst[e];
        int pos = atomicAdd(&g_cursor[d], 1);
        g_ssorted[pos] = src[e];
    }
}

// ---------------- GEMM + self-loop init ----------------
// in = (FIRST ? x : relu(g_agg + b_prev)); a = in @ W
// g_h = a * dinv; g_agg = a * invdeg
// Block: 256 threads = 32 row-groups x 8 col-parts. 4 rows x 8 cols per thread.
// Block covers 128 nodes.
template <bool FIRST>
__global__ __launch_bounds__(256) void gemm_kernel(const float* __restrict__ x,
                                                   const float* __restrict__ W,
                                                   const float* __restrict__ bprev) {
    __shared__ float4 Ws[F * 16];   // [64 rows][16 float4]
    int tid = threadIdx.x;
    const float4* W4 = (const float4*)W;
#pragma unroll
    for (int i = tid; i < F * 16; i += 256) Ws[i] = W4[i];
    __syncthreads();

    int part = tid & 7;                       // 8 parts x 8 cols
    int grp = tid >> 3;                       // 0..31, 4 rows each
    int base = blockIdx.x * 128 + grp * 4;

    const float4* in4 = FIRST ? (const float4*)x : (const float4*)g_agg;
    const float4* b4 = (const float4*)bprev;

    float4 acc[4][2];
#pragma unroll
    for (int r = 0; r < 4; ++r) {
        acc[r][0] = make_float4(0.f, 0.f, 0.f, 0.f);
        acc[r][1] = make_float4(0.f, 0.f, 0.f, 0.f);
    }

#pragma unroll
    for (int k4 = 0; k4 < 16; ++k4) {
        float4 bv;
        if (!FIRST) bv = b4[k4];
        float xs[4][4];
#pragma unroll
        for (int r = 0; r < 4; ++r) {
            int node = base + r;
            float4 xv = make_float4(0.f, 0.f, 0.f, 0.f);
            if (node < NN) {
                xv = in4[(size_t)node * 16 + k4];
                if (!FIRST) {
                    xv.x = fmaxf(xv.x + bv.x, 0.f);
                    xv.y = fmaxf(xv.y + bv.y, 0.f);
                    xv.z = fmaxf(xv.z + bv.z, 0.f);
                    xv.w = fmaxf(xv.w + bv.w, 0.f);
                }
            }
            xs[r][0] = xv.x; xs[r][1] = xv.y; xs[r][2] = xv.z; xs[r][3] = xv.w;
        }
#pragma unroll
        for (int kk = 0; kk < 4; ++kk) {
            const float4* wrow = &Ws[(k4 * 4 + kk) * 16 + part * 2];
            float4 w0 = wrow[0], w1 = wrow[1];
#pragma unroll
            for (int r = 0; r < 4; ++r) {
                float v = xs[r][kk];
                acc[r][0].x = fmaf(v, w0.x, acc[r][0].x);
                acc[r][0].y = fmaf(v, w0.y, acc[r][0].y);
                acc[r][0].z = fmaf(v, w0.z, acc[r][0].z);
                acc[r][0].w = fmaf(v, w0.w, acc[r][0].w);
                acc[r][1].x = fmaf(v, w1.x, acc[r][1].x);
                acc[r][1].y = fmaf(v, w1.y, acc[r][1].y);
                acc[r][1].z = fmaf(v, w1.z, acc[r][1].z);
                acc[r][1].w = fmaf(v, w1.w, acc[r][1].w);
            }
        }
    }

#pragma unroll
    for (int r = 0; r < 4; ++r) {
        int node = base + r;
        if (node >= NN) continue;
        float dv = g_dinv[node];
        float id = g_invdeg[node];
        float4* hr = (float4*)(g_h + (size_t)node * F) + part * 2;
        float4* ar = (float4*)(g_agg + (size_t)node * F) + part * 2;
#pragma unroll
        for (int j = 0; j < 2; ++j) {
            float4 a = acc[r][j];
            hr[j] = make_float4(a.x * dv, a.y * dv, a.z * dv, a.w * dv);
            ar[j] = make_float4(a.x * id, a.y * id, a.z * id, a.w * id);
        }
    }
}

// ---------------- CSR aggregation: one 16-lane group per dst ----------------
// g_agg[d] = self_term + dinv[d] * sum_{s in row(d)} g_h[s]
// LAST: additionally pool relu(out + b3) into g_sums per graph.
template <bool LAST>
__global__ __launch_bounds__(256) void agg_kernel(const int* __restrict__ batch,
                                                  const float* __restrict__ b3) {
    int t = blockIdx.x * blockDim.x + threadIdx.x;
    int d = t >> 4;
    int l = t & 15;
    if (d >= NN) return;
    int start = g_rowstart[d];
    int n = g_deg[d];
    const float4* h4 = (const float4*)g_h;

    float4 acc = make_float4(0.f, 0.f, 0.f, 0.f);
    int i = 0;
    for (; i + 4 <= n; i += 4) {
        int s0 = g_ssorted[start + i];
        int s1 = g_ssorted[start + i + 1];
        int s2 = g_ssorted[start + i + 2];
        int s3 = g_ssorted[start + i + 3];
        float4 v0 = h4[(size_t)s0 * 16 + l];
        float4 v1 = h4[(size_t)s1 * 16 + l];
        float4 v2 = h4[(size_t)s2 * 16 + l];
        float4 v3 = h4[(size_t)s3 * 16 + l];
        acc.x += (v0.x + v1.x) + (v2.x + v3.x);
        acc.y += (v0.y + v1.y) + (v2.y + v3.y);
        acc.z += (v0.z + v1.z) + (v2.z + v3.z);
        acc.w += (v0.w + v1.w) + (v2.w + v3.w);
    }
    for (; i < n; ++i) {
        int s0 = g_ssorted[start + i];
        float4 v0 = h4[(size_t)s0 * 16 + l];
        acc.x += v0.x; acc.y += v0.y; acc.z += v0.z; acc.w += v0.w;
    }

    float dd = g_dinv[d];
    float4* ar = (float4*)g_agg + (size_t)d * 16 + l;
    float4 self = *ar;
    float4 out = make_float4(fmaf(acc.x, dd, self.x),
                             fmaf(acc.y, dd, self.y),
                             fmaf(acc.z, dd, self.z),
                             fmaf(acc.w, dd, self.w));
    if (!LAST) {
        *ar = out;
    } else {
        float4 bv = ((const float4*)b3)[l];
        out.x = fmaxf(out.x + bv.x, 0.f);
        out.y = fmaxf(out.y + bv.y, 0.f);
        out.z = fmaxf(out.z + bv.z, 0.f);
        out.w = fmaxf(out.w + bv.w, 0.f);
        int g = batch[d];
        red_add_v4(g_sums + (size_t)g * F + l * 4, out);
    }
}

// out[g] = (sums[g] . Wl) / max(cnt,1) + bl
__global__ void final_kernel(const float* __restrict__ Wl, const float* __restrict__ bl,
                             float* __restrict__ out) {
    int g = threadIdx.x;
    float c = fmaxf(g_cnt[g], 1.0f);
    float acc = 0.f;
#pragma unroll
    for (int f = 0; f < F; ++f) acc = fmaf(g_sums[g * F + f], Wl[f], acc);
    out[g] = acc / c + bl[0];
}

// ---------------- launch ----------------
extern "C" void kernel_launch(void* const* d_in, const int* in_sizes, int n_in,
                              void* d_out, int out_size) {
    const float* x   = (const float*)d_in[0];
    const int* src   = (const int*)d_in[1];
    const int* dst   = (const int*)d_in[2];
    const int* batch = (const int*)d_in[3];
    const float* W1 = (const float*)d_in[4];
    const float* b1 = (const float*)d_in[5];
    const float* W2 = (const float*)d_in[6];
    const float* b2 = (const float*)d_in[7];
    const float* W3 = (const float*)d_in[8];
    const float* b3 = (const float*)d_in[9];
    const float* Wl = (const float*)d_in[10];
    const float* bl = (const float*)d_in[11];
    float* out = (float*)d_out;

    const int NB_NODE = (NN + 255) / 256;        // 196
    const int NB_EDGE = (NE + 255) / 256;        // 3125
    const int NB_GEMM = (NN + 127) / 128;        // 391 (128 nodes per block)
    const int NB_AGG  = (NN * 16 + 255) / 256;   // 3125

    // prep: degrees, dinv, CSR build (scan-based: node-ordered rows)
    zero_kernel<<<NB_NODE, 256>>>();
    deg_kernel<<<NB_EDGE, 256>>>(dst);
    dinv_kernel<<<NB_NODE, 256>>>(batch);
    scan1_kernel<<<NB_SCAN, 256>>>();
    scan2_kernel<<<1, 256>>>();
    scan3_kernel<<<NB_SCAN, 256>>>();
    scatter_kernel<<<NB_EDGE, 256>>>(src, dst);

    // layer 1
    gemm_kernel<true><<<NB_GEMM, 256>>>(x, W1, nullptr);
    agg_kernel<false><<<NB_AGG, 256>>>(batch, b3);
    // layer 2
    gemm_kernel<false><<<NB_GEMM, 256>>>(nullptr, W2, b1);
    agg_kernel<false><<<NB_AGG, 256>>>(batch, b3);
    // layer 3 (+ fused pool)
    gemm_kernel<false><<<NB_GEMM, 256>>>(nullptr, W3, b2);
    agg_kernel<true><<<NB_AGG, 256>>>(batch, b3);

    final_kernel<<<1, 256>>>(Wl, bl, out);
}

// round 6
// speedup vs baseline: 1.1813x; 1.0329x over previous
#include <cuda_runtime.h>
#include <cuda_bf16.h>

#define NN 50000
#define NE 800000
#define NG 256
#define F  64
#define NB_SCAN 196   // ceil(NN/256)

// ---------------- scratch ----------------
__device__ __align__(16) float g_h[NN * F];     // h * dinv[src] (pre-scaled)
__device__ __align__(16) float g_agg[NN * F];   // self-loop init, then full agg
__device__ __align__(16) float g_sums[NG * F];
__device__ float g_cnt[NG];
__device__ float g_dinv[NN];
__device__ float g_invdeg[NN];
__device__ int   g_deg[NN];
__device__ int   g_rowstart[NN];
__device__ int   g_cursor[NN];
__device__ int   g_bsum[NB_SCAN];
__device__ int   g_boff[NB_SCAN];
__device__ int   g_ssorted[NE];

__device__ __forceinline__ void red_add_v4(float* p, float4 v) {
    asm volatile("red.global.add.v4.f32 [%0], {%1, %2, %3, %4};"
                 :: "l"(p), "f"(v.x), "f"(v.y), "f"(v.z), "f"(v.w) : "memory");
}

// ---------------- prep kernels ----------------
__global__ void zero_kernel() {
    int i = blockIdx.x * blockDim.x + threadIdx.x;
    if (i < NN) g_deg[i] = 0;
    if (i < NG * F) g_sums[i] = 0.0f;
    if (i < NG) g_cnt[i] = 0.0f;
}

// 4 edges per thread (int4 load) for MLP
__global__ void deg_kernel(const int4* __restrict__ dst4) {
    int i = blockIdx.x * blockDim.x + threadIdx.x;
    if (i < NE / 4) {
        int4 d = dst4[i];
        atomicAdd(&g_deg[d.x], 1);
        atomicAdd(&g_deg[d.y], 1);
        atomicAdd(&g_deg[d.z], 1);
        atomicAdd(&g_deg[d.w], 1);
    }
}

// scan phase 1 + dinv/invdeg/cnt fused (both consume g_deg)
__global__ void scan1_kernel(const int* __restrict__ batch) {
    __shared__ int s[2][256];
    int tid = threadIdx.x;
    int i = blockIdx.x * 256 + tid;
    int v = (i < NN) ? g_deg[i] : 0;
    s[0][tid] = v;
    if (i < NN) {
        float d = (float)(v + 1);
        g_dinv[i] = rsqrtf(d);
        g_invdeg[i] = 1.0f / d;
        atomicAdd(&g_cnt[batch[i]], 1.0f);
    }
    __syncthreads();
    int cur = 0;
#pragma unroll
    for (int off = 1; off < 256; off <<= 1) {
        int val = s[cur][tid];
        if (tid >= off) val += s[cur][tid - off];
        s[cur ^ 1][tid] = val;
        cur ^= 1;
        __syncthreads();
    }
    int excl = (tid == 0) ? 0 : s[cur][tid - 1];
    if (i < NN) g_rowstart[i] = excl;
    if (tid == 255) g_bsum[blockIdx.x] = s[cur][255];
}

__global__ void scan2_kernel() {
    __shared__ int s[2][256];
    int tid = threadIdx.x;
    s[0][tid] = (tid < NB_SCAN) ? g_bsum[tid] : 0;
    __syncthreads();
    int cur = 0;
#pragma unroll
    for (int off = 1; off < 256; off <<= 1) {
        int val = s[cur][tid];
        if (tid >= off) val += s[cur][tid - off];
        s[cur ^ 1][tid] = val;
        cur ^= 1;
        __syncthreads();
    }
    if (tid < NB_SCAN) g_boff[tid] = (tid == 0) ? 0 : s[cur][tid - 1];
}

__global__ void scan3_kernel() {
    int i = blockIdx.x * 256 + threadIdx.x;
    if (i < NN) {
        int rs = g_rowstart[i] + g_boff[blockIdx.x];
        g_rowstart[i] = rs;
        g_cursor[i] = rs;
    }
}

// 4 edges per thread (int4 loads) for MLP
__global__ void scatter_kernel(const int4* __restrict__ src4, const int4* __restrict__ dst4) {
    int i = blockIdx.x * blockDim.x + threadIdx.x;
    if (i < NE / 4) {
        int4 s = src4[i];
        int4 d = dst4[i];
        int p0 = atomicAdd(&g_cursor[d.x], 1);
        int p1 = atomicAdd(&g_cursor[d.y], 1);
        int p2 = atomicAdd(&g_cursor[d.z], 1);
        int p3 = atomicAdd(&g_cursor[d.w], 1);
        g_ssorted[p0] = s.x;
        g_ssorted[p1] = s.y;
        g_ssorted[p2] = s.z;
        g_ssorted[p3] = s.w;
    }
}

// ---------------- GEMM + self-loop init (R3 config: 4 rows x 16 cols/thread) ----
// in = (FIRST ? x : relu(g_agg + b_prev)); a = in @ W
// g_h = a * dinv; g_agg = a * invdeg
// Block: 128 threads = 32 quads x 4 parts; quad covers 4 nodes; 128 nodes/block.
template <bool FIRST>
__global__ __launch_bounds__(128) void gemm_kernel(const float* __restrict__ x,
                                                   const float* __restrict__ W,
                                                   const float* __restrict__ bprev) {
    __shared__ float4 Ws[F * 16];
    int tid = threadIdx.x;
    const float4* W4 = (const float4*)W;
#pragma unroll
    for (int i = tid; i < F * 16; i += 128) Ws[i] = W4[i];
    __syncthreads();

    int part = tid & 3;
    int quad = tid >> 2;                      // 0..31
    int base = blockIdx.x * 128 + quad * 4;

    const float4* in4 = FIRST ? (const float4*)x : (const float4*)g_agg;
    const float4* b4 = (const float4*)bprev;

    float4 acc[4][4];
#pragma unroll
    for (int r = 0; r < 4; ++r)
#pragma unroll
        for (int j = 0; j < 4; ++j) acc[r][j] = make_float4(0.f, 0.f, 0.f, 0.f);

#pragma unroll
    for (int k4 = 0; k4 < 16; ++k4) {
        float4 bv;
        if (!FIRST) bv = b4[k4];
        float xs[4][4];
#pragma unroll
        for (int r = 0; r < 4; ++r) {
            int node = base + r;
            float4 xv = make_float4(0.f, 0.f, 0.f, 0.f);
            if (node < NN) {
                xv = in4[(size_t)node * 16 + k4];
                if (!FIRST) {
                    xv.x = fmaxf(xv.x + bv.x, 0.f);
                    xv.y = fmaxf(xv.y + bv.y, 0.f);
                    xv.z = fmaxf(xv.z + bv.z, 0.f);
                    xv.w = fmaxf(xv.w + bv.w, 0.f);
                }
            }
            xs[r][0] = xv.x; xs[r][1] = xv.y; xs[r][2] = xv.z; xs[r][3] = xv.w;
        }
#pragma unroll
        for (int kk = 0; kk < 4; ++kk) {
            const float4* wrow = &Ws[(k4 * 4 + kk) * 16 + part * 4];
            float4 w0 = wrow[0], w1 = wrow[1], w2 = wrow[2], w3 = wrow[3];
#pragma unroll
            for (int r = 0; r < 4; ++r) {
                float v = xs[r][kk];
                acc[r][0].x = fmaf(v, w0.x, acc[r][0].x);
                acc[r][0].y = fmaf(v, w0.y, acc[r][0].y);
                acc[r][0].z = fmaf(v, w0.z, acc[r][0].z);
                acc[r][0].w = fmaf(v, w0.w, acc[r][0].w);
                acc[r][1].x = fmaf(v, w1.x, acc[r][1].x);
                acc[r][1].y = fmaf(v, w1.y, acc[r][1].y);
                acc[r][1].z = fmaf(v, w1.z, acc[r][1].z);
                acc[r][1].w = fmaf(v, w1.w, acc[r][1].w);
                acc[r][2].x = fmaf(v, w2.x, acc[r][2].x);
                acc[r][2].y = fmaf(v, w2.y, acc[r][2].y);
                acc[r][2].z = fmaf(v, w2.z, acc[r][2].z);
                acc[r][2].w = fmaf(v, w2.w, acc[r][2].w);
                acc[r][3].x = fmaf(v, w3.x, acc[r][3].x);
                acc[r][3].y = fmaf(v, w3.y, acc[r][3].y);
                acc[r][3].z = fmaf(v, w3.z, acc[r][3].z);
                acc[r][3].w = fmaf(v, w3.w, acc[r][3].w);
            }
        }
    }

#pragma unroll
    for (int r = 0; r < 4; ++r) {
        int node = base + r;
        if (node >= NN) continue;
        float dv = g_dinv[node];
        float id = g_invdeg[node];
        float4* hr = (float4*)(g_h + (size_t)node * F) + part * 4;
        float4* ar = (float4*)(g_agg + (size_t)node * F) + part * 4;
#pragma unroll
        for (int j = 0; j < 4; ++j) {
            float4 a = acc[r][j];
            hr[j] = make_float4(a.x * dv, a.y * dv, a.z * dv, a.w * dv);
            ar[j] = make_float4(a.x * id, a.y * id, a.z * id, a.w * id);
        }
    }
}

// ---------------- CSR aggregation: one 16-lane group per dst ----------------
// g_agg[d] = self_term + dinv[d] * sum_{s in row(d)} g_h[s]
// LAST: additionally pool relu(out + b3) into g_sums per graph.
template <bool LAST>
__global__ __launch_bounds__(256) void agg_kernel(const int* __restrict__ batch,
                                                  const float* __restrict__ b3) {
    int t = blockIdx.x * blockDim.x + threadIdx.x;
    int d = t >> 4;
    int l = t & 15;
    if (d >= NN) return;
    int start = g_rowstart[d];
    int n = g_deg[d];
    const float4* h4 = (const float4*)g_h;

    float4 acc = make_float4(0.f, 0.f, 0.f, 0.f);
    int i = 0;
    for (; i + 4 <= n; i += 4) {
        int s0 = g_ssorted[start + i];
        int s1 = g_ssorted[start + i + 1];
        int s2 = g_ssorted[start + i + 2];
        int s3 = g_ssorted[start + i + 3];
        float4 v0 = h4[(size_t)s0 * 16 + l];
        float4 v1 = h4[(size_t)s1 * 16 + l];
        float4 v2 = h4[(size_t)s2 * 16 + l];
        float4 v3 = h4[(size_t)s3 * 16 + l];
        acc.x += (v0.x + v1.x) + (v2.x + v3.x);
        acc.y += (v0.y + v1.y) + (v2.y + v3.y);
        acc.z += (v0.z + v1.z) + (v2.z + v3.z);
        acc.w += (v0.w + v1.w) + (v2.w + v3.w);
    }
    for (; i < n; ++i) {
        int s0 = g_ssorted[start + i];
        float4 v0 = h4[(size_t)s0 * 16 + l];
        acc.x += v0.x; acc.y += v0.y; acc.z += v0.z; acc.w += v0.w;
    }

    float dd = g_dinv[d];
    float4* ar = (float4*)g_agg + (size_t)d * 16 + l;
    float4 self = *ar;
    float4 out = make_float4(fmaf(acc.x, dd, self.x),
                             fmaf(acc.y, dd, self.y),
                             fmaf(acc.z, dd, self.z),
                             fmaf(acc.w, dd, self.w));
    if (!LAST) {
        *ar = out;
    } else {
        float4 bv = ((const float4*)b3)[l];
        out.x = fmaxf(out.x + bv.x, 0.f);
        out.y = fmaxf(out.y + bv.y, 0.f);
        out.z = fmaxf(out.z + bv.z, 0.f);
        out.w = fmaxf(out.w + bv.w, 0.f);
        int g = batch[d];
        red_add_v4(g_sums + (size_t)g * F + l * 4, out);
    }
}

// out[g] = (sums[g] . Wl) / max(cnt,1) + bl
__global__ void final_kernel(const float* __restrict__ Wl, const float* __restrict__ bl,
                             float* __restrict__ out) {
    int g = threadIdx.x;
    float c = fmaxf(g_cnt[g], 1.0f);
    float acc = 0.f;
#pragma unroll
    for (int f = 0; f < F; ++f) acc = fmaf(g_sums[g * F + f], Wl[f], acc);
    out[g] = acc / c + bl[0];
}

// ---------------- launch ----------------
extern "C" void kernel_launch(void* const* d_in, const int* in_sizes, int n_in,
                              void* d_out, int out_size) {
    const float* x   = (const float*)d_in[0];
    const int* src   = (const int*)d_in[1];
    const int* dst   = (const int*)d_in[2];
    const int* batch = (const int*)d_in[3];
    const float* W1 = (const float*)d_in[4];
    const float* b1 = (const float*)d_in[5];
    const float* W2 = (const float*)d_in[6];
    const float* b2 = (const float*)d_in[7];
    const float* W3 = (const float*)d_in[8];
    const float* b3 = (const float*)d_in[9];
    const float* Wl = (const float*)d_in[10];
    const float* bl = (const float*)d_in[11];
    float* out = (float*)d_out;

    const int NB_NODE = (NN + 255) / 256;          // 196
    const int NB_E4   = (NE / 4 + 255) / 256;      // 782
    const int NB_GEMM = (NN + 127) / 128;          // 391
    const int NB_AGG  = (NN * 16 + 255) / 256;     // 3125

    // prep: degrees, CSR build (scan keeps node-ordered rows; dinv fused in scan1)
    zero_kernel<<<NB_NODE, 256>>>();
    deg_kernel<<<NB_E4, 256>>>((const int4*)dst);
    scan1_kernel<<<NB_SCAN, 256>>>(batch);
    scan2_kernel<<<1, 256>>>();
    scan3_kernel<<<NB_SCAN, 256>>>();
    scatter_kernel<<<NB_E4, 256>>>((const int4*)src, (const int4*)dst);

    // layer 1
    gemm_kernel<true><<<NB_GEMM, 128>>>(x, W1, nullptr);
    agg_kernel<false><<<NB_AGG, 256>>>(batch, b3);
    // layer 2
    gemm_kernel<false><<<NB_GEMM, 128>>>(nullptr, W2, b1);
    agg_kernel<false><<<NB_AGG, 256>>>(batch, b3);
    // layer 3 (+ fused pool)
    gemm_kernel<false><<<NB_GEMM, 128>>>(nullptr, W3, b2);
    agg_kernel<true><<<NB_AGG, 256>>>(batch, b3);

    final_kernel<<<1, 256>>>(Wl, bl, out);
}

// round 7
// speedup vs baseline: 1.1857x; 1.0037x over previous
#include <cuda_runtime.h>
#include <cuda_fp16.h>

#define NN 50000
#define NE 800000
#define NG 256
#define F  64
#define NB_SCAN 196   // ceil(NN/256)

// ---------------- scratch ----------------
__device__ __align__(16) __half g_hh[NN * F];   // h * dinv[src], fp16 (gather payload)
__device__ __align__(16) float g_agg[NN * F];   // self-loop init, then full agg (fp32)
__device__ __align__(16) float g_sums[NG * F];
__device__ float g_cnt[NG];
__device__ float g_dinv[NN];
__device__ float g_invdeg[NN];
__device__ int   g_deg[NN];
__device__ int   g_rowstart[NN];
__device__ int   g_cursor[NN];
__device__ int   g_bsum[NB_SCAN];
__device__ int   g_boff[NB_SCAN];
__device__ int   g_ssorted[NE];

__device__ __forceinline__ void red_add_v4(float* p, float4 v) {
    asm volatile("red.global.add.v4.f32 [%0], {%1, %2, %3, %4};"
                 :: "l"(p), "f"(v.x), "f"(v.y), "f"(v.z), "f"(v.w) : "memory");
}

// ---------------- prep kernels (R3 structure) ----------------
__global__ void zero_kernel() {
    int i = blockIdx.x * blockDim.x + threadIdx.x;
    if (i < NN) g_deg[i] = 0;
    if (i < NG * F) g_sums[i] = 0.0f;
    if (i < NG) g_cnt[i] = 0.0f;
}

__global__ void deg_kernel(const int* __restrict__ dst) {
    int e = blockIdx.x * blockDim.x + threadIdx.x;
    if (e < NE) atomicAdd(&g_deg[dst[e]], 1);
}

__global__ void dinv_kernel(const int* __restrict__ batch) {
    int i = blockIdx.x * blockDim.x + threadIdx.x;
    if (i < NN) {
        float d = (float)(g_deg[i] + 1);
        g_dinv[i] = rsqrtf(d);
        g_invdeg[i] = 1.0f / d;
        atomicAdd(&g_cnt[batch[i]], 1.0f);
    }
}

__global__ void scan1_kernel() {
    __shared__ int s[2][256];
    int tid = threadIdx.x;
    int i = blockIdx.x * 256 + tid;
    int v = (i < NN) ? g_deg[i] : 0;
    s[0][tid] = v;
    __syncthreads();
    int cur = 0;
#pragma unroll
    for (int off = 1; off < 256; off <<= 1) {
        int val = s[cur][tid];
        if (tid >= off) val += s[cur][tid - off];
        s[cur ^ 1][tid] = val;
        cur ^= 1;
        __syncthreads();
    }
    int excl = (tid == 0) ? 0 : s[cur][tid - 1];
    if (i < NN) g_rowstart[i] = excl;
    if (tid == 255) g_bsum[blockIdx.x] = s[cur][255];
}

__global__ void scan2_kernel() {
    __shared__ int s[2][256];
    int tid = threadIdx.x;
    s[0][tid] = (tid < NB_SCAN) ? g_bsum[tid] : 0;
    __syncthreads();
    int cur = 0;
#pragma unroll
    for (int off = 1; off < 256; off <<= 1) {
        int val = s[cur][tid];
        if (tid >= off) val += s[cur][tid - off];
        s[cur ^ 1][tid] = val;
        cur ^= 1;
        __syncthreads();
    }
    if (tid < NB_SCAN) g_boff[tid] = (tid == 0) ? 0 : s[cur][tid - 1];
}

__global__ void scan3_kernel() {
    int i = blockIdx.x * 256 + threadIdx.x;
    if (i < NN) {
        int rs = g_rowstart[i] + g_boff[blockIdx.x];
        g_rowstart[i] = rs;
        g_cursor[i] = rs;
    }
}

__global__ void scatter_kernel(const int* __restrict__ src, const int* __restrict__ dst) {
    int e = blockIdx.x * blockDim.x + threadIdx.x;
    if (e < NE) {
        int d = dst[e];
        int pos = atomicAdd(&g_cursor[d], 1);
        g_ssorted[pos] = src[e];
    }
}

// ---------------- GEMM + self-loop init (R3 config: 4 rows x 16 cols/thread) ----
// in = (FIRST ? x : relu(g_agg + b_prev)); a = in @ W
// g_hh = half(a * dinv); g_agg = a * invdeg
// Block: 128 threads = 32 quads x 4 parts; 128 nodes/block.
template <bool FIRST>
__global__ __launch_bounds__(128) void gemm_kernel(const float* __restrict__ x,
                                                   const float* __restrict__ W,
                                                   const float* __restrict__ bprev) {
    __shared__ float4 Ws[F * 16];
    int tid = threadIdx.x;
    const float4* W4 = (const float4*)W;
#pragma unroll
    for (int i = tid; i < F * 16; i += 128) Ws[i] = W4[i];
    __syncthreads();

    int part = tid & 3;
    int quad = tid >> 2;
    int base = blockIdx.x * 128 + quad * 4;

    const float4* in4 = FIRST ? (const float4*)x : (const float4*)g_agg;
    const float4* b4 = (const float4*)bprev;

    float4 acc[4][4];
#pragma unroll
    for (int r = 0; r < 4; ++r)
#pragma unroll
        for (int j = 0; j < 4; ++j) acc[r][j] = make_float4(0.f, 0.f, 0.f, 0.f);

#pragma unroll
    for (int k4 = 0; k4 < 16; ++k4) {
        float4 bv;
        if (!FIRST) bv = b4[k4];
        float xs[4][4];
#pragma unroll
        for (int r = 0; r < 4; ++r) {
            int node = base + r;
            float4 xv = make_float4(0.f, 0.f, 0.f, 0.f);
            if (node < NN) {
                xv = in4[(size_t)node * 16 + k4];
                if (!FIRST) {
                    xv.x = fmaxf(xv.x + bv.x, 0.f);
                    xv.y = fmaxf(xv.y + bv.y, 0.f);
                    xv.z = fmaxf(xv.z + bv.z, 0.f);
                    xv.w = fmaxf(xv.w + bv.w, 0.f);
                }
            }
            xs[r][0] = xv.x; xs[r][1] = xv.y; xs[r][2] = xv.z; xs[r][3] = xv.w;
        }
#pragma unroll
        for (int kk = 0; kk < 4; ++kk) {
            const float4* wrow = &Ws[(k4 * 4 + kk) * 16 + part * 4];
            float4 w0 = wrow[0], w1 = wrow[1], w2 = wrow[2], w3 = wrow[3];
#pragma unroll
            for (int r = 0; r < 4; ++r) {
                float v = xs[r][kk];
                acc[r][0].x = fmaf(v, w0.x, acc[r][0].x);
                acc[r][0].y = fmaf(v, w0.y, acc[r][0].y);
                acc[r][0].z = fmaf(v, w0.z, acc[r][0].z);
                acc[r][0].w = fmaf(v, w0.w, acc[r][0].w);
                acc[r][1].x = fmaf(v, w1.x, acc[r][1].x);
                acc[r][1].y = fmaf(v, w1.y, acc[r][1].y);
                acc[r][1].z = fmaf(v, w1.z, acc[r][1].z);
                acc[r][1].w = fmaf(v, w1.w, acc[r][1].w);
                acc[r][2].x = fmaf(v, w2.x, acc[r][2].x);
                acc[r][2].y = fmaf(v, w2.y, acc[r][2].y);
                acc[r][2].z = fmaf(v, w2.z, acc[r][2].z);
                acc[r][2].w = fmaf(v, w2.w, acc[r][2].w);
                acc[r][3].x = fmaf(v, w3.x, acc[r][3].x);
                acc[r][3].y = fmaf(v, w3.y, acc[r][3].y);
                acc[r][3].z = fmaf(v, w3.z, acc[r][3].z);
                acc[r][3].w = fmaf(v, w3.w, acc[r][3].w);
            }
        }
    }

#pragma unroll
    for (int r = 0; r < 4; ++r) {
        int node = base + r;
        if (node >= NN) continue;
        float dv = g_dinv[node];
        float id = g_invdeg[node];
        // 16 halfs = 8 half2 = 32 bytes at cols [part*16, part*16+16)
        __half2* hr = (__half2*)(g_hh + (size_t)node * F + part * 16);
        float4* ar = (float4*)(g_agg + (size_t)node * F) + part * 4;
#pragma unroll
        for (int j = 0; j < 4; ++j) {
            float4 a = acc[r][j];
            hr[j * 2 + 0] = __floats2half2_rn(a.x * dv, a.y * dv);
            hr[j * 2 + 1] = __floats2half2_rn(a.z * dv, a.w * dv);
            ar[j] = make_float4(a.x * id, a.y * id, a.z * id, a.w * id);
        }
    }
}

// ---------------- CSR aggregation: one 8-lane group per dst (fp16 gather) ------
// g_agg[d] = self_term + dinv[d] * sum_{s in row(d)} half(g_hh[s])
// LAST: additionally pool relu(out + b3) into g_sums per graph.
template <bool LAST>
__global__ __launch_bounds__(256) void agg_kernel(const int* __restrict__ batch,
                                                  const float* __restrict__ b3) {
    int t = blockIdx.x * blockDim.x + threadIdx.x;
    int d = t >> 3;
    int l = t & 7;            // 8 lanes x 8 features (16B) per lane
    if (d >= NN) return;
    int start = g_rowstart[d];
    int n = g_deg[d];
    const uint4* h4 = (const uint4*)g_hh;   // one uint4 = 8 halfs

    float acc[8];
#pragma unroll
    for (int j = 0; j < 8; ++j) acc[j] = 0.f;

#pragma unroll 1
    for (int i = 0; i < n; ++i) {
        int s0 = g_ssorted[start + i];
        uint4 raw = h4[(size_t)s0 * 8 + l];
        const __half2* p = (const __half2*)&raw;
#pragma unroll
        for (int j = 0; j < 4; ++j) {
            float2 f = __half22float2(p[j]);
            acc[j * 2 + 0] += f.x;
            acc[j * 2 + 1] += f.y;
        }
    }

    float dd = g_dinv[d];
    float4* ar = (float4*)(g_agg + (size_t)d * F + l * 8);
    float4 s0v = ar[0];
    float4 s1v = ar[1];
    float4 o0 = make_float4(fmaf(acc[0], dd, s0v.x), fmaf(acc[1], dd, s0v.y),
                            fmaf(acc[2], dd, s0v.z), fmaf(acc[3], dd, s0v.w));
    float4 o1 = make_float4(fmaf(acc[4], dd, s1v.x), fmaf(acc[5], dd, s1v.y),
                            fmaf(acc[6], dd, s1v.z), fmaf(acc[7], dd, s1v.w));
    if (!LAST) {
        ar[0] = o0;
        ar[1] = o1;
    } else {
        float4 b0 = ((const float4*)b3)[l * 2 + 0];
        float4 b1 = ((const float4*)b3)[l * 2 + 1];
        o0.x = fmaxf(o0.x + b0.x, 0.f); o0.y = fmaxf(o0.y + b0.y, 0.f);
        o0.z = fmaxf(o0.z + b0.z, 0.f); o0.w = fmaxf(o0.w + b0.w, 0.f);
        o1.x = fmaxf(o1.x + b1.x, 0.f); o1.y = fmaxf(o1.y + b1.y, 0.f);
        o1.z = fmaxf(o1.z + b1.z, 0.f); o1.w = fmaxf(o1.w + b1.w, 0.f);
        int g = batch[d];
        red_add_v4(g_sums + (size_t)g * F + l * 8, o0);
        red_add_v4(g_sums + (size_t)g * F + l * 8 + 4, o1);
    }
}

// out[g] = (sums[g] . Wl) / max(cnt,1) + bl
__global__ void final_kernel(const float* __restrict__ Wl, const float* __restrict__ bl,
                             float* __restrict__ out) {
    int g = threadIdx.x;
    float c = fmaxf(g_cnt[g], 1.0f);
    float acc = 0.f;
#pragma unroll
    for (int f = 0; f < F; ++f) acc = fmaf(g_sums[g * F + f], Wl[f], acc);
    out[g] = acc / c + bl[0];
}

// ---------------- launch ----------------
extern "C" void kernel_launch(void* const* d_in, const int* in_sizes, int n_in,
                              void* d_out, int out_size) {
    const float* x   = (const float*)d_in[0];
    const int* src   = (const int*)d_in[1];
    const int* dst   = (const int*)d_in[2];
    const int* batch = (const int*)d_in[3];
    const float* W1 = (const float*)d_in[4];
    const float* b1 = (const float*)d_in[5];
    const float* W2 = (const float*)d_in[6];
    const float* b2 = (const float*)d_in[7];
    const float* W3 = (const float*)d_in[8];
    const float* b3 = (const float*)d_in[9];
    const float* Wl = (const float*)d_in[10];
    const float* bl = (const float*)d_in[11];
    float* out = (float*)d_out;

    const int NB_NODE = (NN + 255) / 256;        // 196
    const int NB_EDGE = (NE + 255) / 256;        // 3125
    const int NB_GEMM = (NN + 127) / 128;        // 391
    const int NB_AGG  = (NN * 8 + 255) / 256;    // 1563

    // prep: degrees, dinv, scan-based CSR (node-ordered rows)
    zero_kernel<<<NB_NODE, 256>>>();
    deg_kernel<<<NB_EDGE, 256>>>(dst);
    dinv_kernel<<<NB_NODE, 256>>>(batch);
    scan1_kernel<<<NB_SCAN, 256>>>();
    scan2_kernel<<<1, 256>>>();
    scan3_kernel<<<NB_SCAN, 256>>>();
    scatter_kernel<<<NB_EDGE, 256>>>(src, dst);

    // layer 1
    gemm_kernel<true><<<NB_GEMM, 128>>>(x, W1, nullptr);
    agg_kernel<false><<<NB_AGG, 256>>>(batch, b3);
    // layer 2
    gemm_kernel<false><<<NB_GEMM, 128>>>(nullptr, W2, b1);
    agg_kernel<false><<<NB_AGG, 256>>>(batch, b3);
    // layer 3 (+ fused pool)
    gemm_kernel<false><<<NB_GEMM, 128>>>(nullptr, W3, b2);
    agg_kernel<true><<<NB_AGG, 256>>>(batch, b3);

    final_kernel<<<1, 256>>>(Wl, bl, out);
}

// round 8
// speedup vs baseline: 1.2630x; 1.0652x over previous
#include <cuda_runtime.h>
#include <cuda_fp16.h>

#define NN 50000
#define NE 800000
#define NG 256
#define F  64
#define NB_SCAN 196   // ceil(NN/256)

// ---------------- scratch ----------------
__device__ __align__(16) __half g_hh[NN * F];   // h * dinv[src], fp16 (gather payload)
__device__ __align__(16) float g_agg[NN * F];   // self-loop init, then full agg (fp32)
__device__ __align__(16) float g_sums[NG * F];
__device__ float g_cnt[NG];
__device__ float g_dinv[NN];
__device__ float g_invdeg[NN];
__device__ int   g_deg[NN];
__device__ int   g_rowstart[NN];
__device__ int   g_cursor[NN];
__device__ int   g_bsum[NB_SCAN];
__device__ int   g_boff[NB_SCAN];
__device__ int   g_ssorted[NE];

__device__ __forceinline__ void red_add_v4(float* p, float4 v) {
    asm volatile("red.global.add.v4.f32 [%0], {%1, %2, %3, %4};"
                 :: "l"(p), "f"(v.x), "f"(v.y), "f"(v.z), "f"(v.w) : "memory");
}

// ---------------- prep kernels (R3 structure) ----------------
__global__ void zero_kernel() {
    int i = blockIdx.x * blockDim.x + threadIdx.x;
    if (i < NN) g_deg[i] = 0;
    if (i < NG * F) g_sums[i] = 0.0f;
    if (i < NG) g_cnt[i] = 0.0f;
}

__global__ void deg_kernel(const int* __restrict__ dst) {
    int e = blockIdx.x * blockDim.x + threadIdx.x;
    if (e < NE) atomicAdd(&g_deg[dst[e]], 1);
}

__global__ void dinv_kernel(const int* __restrict__ batch) {
    int i = blockIdx.x * blockDim.x + threadIdx.x;
    if (i < NN) {
        float d = (float)(g_deg[i] + 1);
        g_dinv[i] = rsqrtf(d);
        g_invdeg[i] = 1.0f / d;
        atomicAdd(&g_cnt[batch[i]], 1.0f);
    }
}

__global__ void scan1_kernel() {
    __shared__ int s[2][256];
    int tid = threadIdx.x;
    int i = blockIdx.x * 256 + tid;
    int v = (i < NN) ? g_deg[i] : 0;
    s[0][tid] = v;
    __syncthreads();
    int cur = 0;
#pragma unroll
    for (int off = 1; off < 256; off <<= 1) {
        int val = s[cur][tid];
        if (tid >= off) val += s[cur][tid - off];
        s[cur ^ 1][tid] = val;
        cur ^= 1;
        __syncthreads();
    }
    int excl = (tid == 0) ? 0 : s[cur][tid - 1];
    if (i < NN) g_rowstart[i] = excl;
    if (tid == 255) g_bsum[blockIdx.x] = s[cur][255];
}

__global__ void scan2_kernel() {
    __shared__ int s[2][256];
    int tid = threadIdx.x;
    s[0][tid] = (tid < NB_SCAN) ? g_bsum[tid] : 0;
    __syncthreads();
    int cur = 0;
#pragma unroll
    for (int off = 1; off < 256; off <<= 1) {
        int val = s[cur][tid];
        if (tid >= off) val += s[cur][tid - off];
        s[cur ^ 1][tid] = val;
        cur ^= 1;
        __syncthreads();
    }
    if (tid < NB_SCAN) g_boff[tid] = (tid == 0) ? 0 : s[cur][tid - 1];
}

__global__ void scan3_kernel() {
    int i = blockIdx.x * 256 + threadIdx.x;
    if (i < NN) {
        int rs = g_rowstart[i] + g_boff[blockIdx.x];
        g_rowstart[i] = rs;
        g_cursor[i] = rs;
    }
}

__global__ void scatter_kernel(const int* __restrict__ src, const int* __restrict__ dst) {
    int e = blockIdx.x * blockDim.x + threadIdx.x;
    if (e < NE) {
        int d = dst[e];
        int pos = atomicAdd(&g_cursor[d], 1);
        g_ssorted[pos] = src[e];
    }
}

// ---------------- GEMM + self-loop init (R3 config: 4 rows x 16 cols/thread) ----
// in = (FIRST ? x : relu(g_agg + b_prev)); a = in @ W
// g_hh = half(a * dinv); g_agg = a * invdeg
// Block: 128 threads = 32 quads x 4 parts; 128 nodes/block.
template <bool FIRST>
__global__ __launch_bounds__(128) void gemm_kernel(const float* __restrict__ x,
                                                   const float* __restrict__ W,
                                                   const float* __restrict__ bprev) {
    __shared__ float4 Ws[F * 16];
    int tid = threadIdx.x;
    const float4* W4 = (const float4*)W;
#pragma unroll
    for (int i = tid; i < F * 16; i += 128) Ws[i] = W4[i];
    __syncthreads();

    int part = tid & 3;
    int quad = tid >> 2;
    int base = blockIdx.x * 128 + quad * 4;

    const float4* in4 = FIRST ? (const float4*)x : (const float4*)g_agg;
    const float4* b4 = (const float4*)bprev;

    float4 acc[4][4];
#pragma unroll
    for (int r = 0; r < 4; ++r)
#pragma unroll
        for (int j = 0; j < 4; ++j) acc[r][j] = make_float4(0.f, 0.f, 0.f, 0.f);

#pragma unroll
    for (int k4 = 0; k4 < 16; ++k4) {
        float4 bv;
        if (!FIRST) bv = b4[k4];
        float xs[4][4];
#pragma unroll
        for (int r = 0; r < 4; ++r) {
            int node = base + r;
            float4 xv = make_float4(0.f, 0.f, 0.f, 0.f);
            if (node < NN) {
                xv = in4[(size_t)node * 16 + k4];
                if (!FIRST) {
                    xv.x = fmaxf(xv.x + bv.x, 0.f);
                    xv.y = fmaxf(xv.y + bv.y, 0.f);
                    xv.z = fmaxf(xv.z + bv.z, 0.f);
                    xv.w = fmaxf(xv.w + bv.w, 0.f);
                }
            }
            xs[r][0] = xv.x; xs[r][1] = xv.y; xs[r][2] = xv.z; xs[r][3] = xv.w;
        }
#pragma unroll
        for (int kk = 0; kk < 4; ++kk) {
            const float4* wrow = &Ws[(k4 * 4 + kk) * 16 + part * 4];
            float4 w0 = wrow[0], w1 = wrow[1], w2 = wrow[2], w3 = wrow[3];
#pragma unroll
            for (int r = 0; r < 4; ++r) {
                float v = xs[r][kk];
                acc[r][0].x = fmaf(v, w0.x, acc[r][0].x);
                acc[r][0].y = fmaf(v, w0.y, acc[r][0].y);
                acc[r][0].z = fmaf(v, w0.z, acc[r][0].z);
                acc[r][0].w = fmaf(v, w0.w, acc[r][0].w);
                acc[r][1].x = fmaf(v, w1.x, acc[r][1].x);
                acc[r][1].y = fmaf(v, w1.y, acc[r][1].y);
                acc[r][1].z = fmaf(v, w1.z, acc[r][1].z);
                acc[r][1].w = fmaf(v, w1.w, acc[r][1].w);
                acc[r][2].x = fmaf(v, w2.x, acc[r][2].x);
                acc[r][2].y = fmaf(v, w2.y, acc[r][2].y);
                acc[r][2].z = fmaf(v, w2.z, acc[r][2].z);
                acc[r][2].w = fmaf(v, w2.w, acc[r][2].w);
                acc[r][3].x = fmaf(v, w3.x, acc[r][3].x);
                acc[r][3].y = fmaf(v, w3.y, acc[r][3].y);
                acc[r][3].z = fmaf(v, w3.z, acc[r][3].z);
                acc[r][3].w = fmaf(v, w3.w, acc[r][3].w);
            }
        }
    }

#pragma unroll
    for (int r = 0; r < 4; ++r) {
        int node = base + r;
        if (node >= NN) continue;
        float dv = g_dinv[node];
        float id = g_invdeg[node];
        __half2* hr = (__half2*)(g_hh + (size_t)node * F + part * 16);
        float4* ar = (float4*)(g_agg + (size_t)node * F) + part * 4;
#pragma unroll
        for (int j = 0; j < 4; ++j) {
            float4 a = acc[r][j];
            hr[j * 2 + 0] = __floats2half2_rn(a.x * dv, a.y * dv);
            hr[j * 2 + 1] = __floats2half2_rn(a.z * dv, a.w * dv);
            ar[j] = make_float4(a.x * id, a.y * id, a.z * id, a.w * id);
        }
    }
}

// ---------------- CSR aggregation: 8-lane group per dst, fp16 gather, MLP=4 ----
// g_agg[d] = self_term + dinv[d] * sum_{s in row(d)} half(g_hh[s])
// LAST: additionally pool relu(out + b3) into g_sums per graph.
template <bool LAST>
__global__ __launch_bounds__(256) void agg_kernel(const int* __restrict__ batch,
                                                  const float* __restrict__ b3) {
    int t = blockIdx.x * blockDim.x + threadIdx.x;
    int d = t >> 3;
    int l = t & 7;            // 8 lanes x 8 features (16B) per lane
    if (d >= NN) return;
    int start = g_rowstart[d];
    int n = g_deg[d];
    const uint4* h4 = (const uint4*)g_hh;   // one uint4 = 8 halfs

    float acc[8];
#pragma unroll
    for (int j = 0; j < 8; ++j) acc[j] = 0.f;

    int i = 0;
    for (; i + 4 <= n; i += 4) {
        int s0 = g_ssorted[start + i];
        int s1 = g_ssorted[start + i + 1];
        int s2 = g_ssorted[start + i + 2];
        int s3 = g_ssorted[start + i + 3];
        uint4 r0 = h4[(size_t)s0 * 8 + l];
        uint4 r1 = h4[(size_t)s1 * 8 + l];
        uint4 r2 = h4[(size_t)s2 * 8 + l];
        uint4 r3 = h4[(size_t)s3 * 8 + l];
        const __half2* p0 = (const __half2*)&r0;
        const __half2* p1 = (const __half2*)&r1;
        const __half2* p2 = (const __half2*)&r2;
        const __half2* p3 = (const __half2*)&r3;
#pragma unroll
        for (int j = 0; j < 4; ++j) {
            float2 f0 = __half22float2(p0[j]);
            float2 f1 = __half22float2(p1[j]);
            float2 f2 = __half22float2(p2[j]);
            float2 f3 = __half22float2(p3[j]);
            acc[j * 2 + 0] += (f0.x + f1.x) + (f2.x + f3.x);
            acc[j * 2 + 1] += (f0.y + f1.y) + (f2.y + f3.y);
        }
    }
    for (; i < n; ++i) {
        int s0 = g_ssorted[start + i];
        uint4 r0 = h4[(size_t)s0 * 8 + l];
        const __half2* p0 = (const __half2*)&r0;
#pragma unroll
        for (int j = 0; j < 4; ++j) {
            float2 f0 = __half22float2(p0[j]);
            acc[j * 2 + 0] += f0.x;
            acc[j * 2 + 1] += f0.y;
        }
    }

    float dd = g_dinv[d];
    float4* ar = (float4*)(g_agg + (size_t)d * F + l * 8);
    float4 s0v = ar[0];
    float4 s1v = ar[1];
    float4 o0 = make_float4(fmaf(acc[0], dd, s0v.x), fmaf(acc[1], dd, s0v.y),
                            fmaf(acc[2], dd, s0v.z), fmaf(acc[3], dd, s0v.w));
    float4 o1 = make_float4(fmaf(acc[4], dd, s1v.x), fmaf(acc[5], dd, s1v.y),
                            fmaf(acc[6], dd, s1v.z), fmaf(acc[7], dd, s1v.w));
    if (!LAST) {
        ar[0] = o0;
        ar[1] = o1;
    } else {
        float4 b0 = ((const float4*)b3)[l * 2 + 0];
        float4 b1 = ((const float4*)b3)[l * 2 + 1];
        o0.x = fmaxf(o0.x + b0.x, 0.f); o0.y = fmaxf(o0.y + b0.y, 0.f);
        o0.z = fmaxf(o0.z + b0.z, 0.f); o0.w = fmaxf(o0.w + b0.w, 0.f);
        o1.x = fmaxf(o1.x + b1.x, 0.f); o1.y = fmaxf(o1.y + b1.y, 0.f);
        o1.z = fmaxf(o1.z + b1.z, 0.f); o1.w = fmaxf(o1.w + b1.w, 0.f);
        int g = batch[d];
        red_add_v4(g_sums + (size_t)g * F + l * 8, o0);
        red_add_v4(g_sums + (size_t)g * F + l * 8 + 4, o1);
    }
}

// out[g] = (sums[g] . Wl) / max(cnt,1) + bl
__global__ void final_kernel(const float* __restrict__ Wl, const float* __restrict__ bl,
                             float* __restrict__ out) {
    int g = threadIdx.x;
    float c = fmaxf(g_cnt[g], 1.0f);
    float acc = 0.f;
#pragma unroll
    for (int f = 0; f < F; ++f) acc = fmaf(g_sums[g * F + f], Wl[f], acc);
    out[g] = acc / c + bl[0];
}

// ---------------- launch ----------------
extern "C" void kernel_launch(void* const* d_in, const int* in_sizes, int n_in,
                              void* d_out, int out_size) {
    const float* x   = (const float*)d_in[0];
    const int* src   = (const int*)d_in[1];
    const int* dst   = (const int*)d_in[2];
    const int* batch = (const int*)d_in[3];
    const float* W1 = (const float*)d_in[4];
    const float* b1 = (const float*)d_in[5];
    const float* W2 = (const float*)d_in[6];
    const float* b2 = (const float*)d_in[7];
    const float* W3 = (const float*)d_in[8];
    const float* b3 = (const float*)d_in[9];
    const float* Wl = (const float*)d_in[10];
    const float* bl = (const float*)d_in[11];
    float* out = (float*)d_out;

    const int NB_NODE = (NN + 255) / 256;        // 196
    const int NB_EDGE = (NE + 255) / 256;        // 3125
    const int NB_GEMM = (NN + 127) / 128;        // 391
    const int NB_AGG  = (NN * 8 + 255) / 256;    // 1563

    // prep: degrees, dinv, scan-based CSR (node-ordered rows)
    zero_kernel<<<NB_NODE, 256>>>();
    deg_kernel<<<NB_EDGE, 256>>>(dst);
    dinv_kernel<<<NB_NODE, 256>>>(batch);
    scan1_kernel<<<NB_SCAN, 256>>>();
    scan2_kernel<<<1, 256>>>();
    scan3_kernel<<<NB_SCAN, 256>>>();
    scatter_kernel<<<NB_EDGE, 256>>>(src, dst);

    // layer 1
    gemm_kernel<true><<<NB_GEMM, 128>>>(x, W1, nullptr);
    agg_kernel<false><<<NB_AGG, 256>>>(batch, b3);
    // layer 2
    gemm_kernel<false><<<NB_GEMM, 128>>>(nullptr, W2, b1);
    agg_kernel<false><<<NB_AGG, 256>>>(batch, b3);
    // layer 3 (+ fused pool)
    gemm_kernel<false><<<NB_GEMM, 128>>>(nullptr, W3, b2);
    agg_kernel<true><<<NB_AGG, 256>>>(batch, b3);

    final_kernel<<<1, 256>>>(Wl, bl, out);
}

// round 9
// speedup vs baseline: 1.2917x; 1.0228x over previous
#include <cuda_runtime.h>
#include <cuda_fp16.h>

#define NN 50000
#define NE 800000
#define NG 256
#define F  64

// ---------------- scratch ----------------
__device__ __align__(16) __half g_hh[NN * F];   // h * dinv[src], fp16 (gather payload)
__device__ __align__(16) float g_agg[NN * F];   // self-loop init, then full agg (fp32)
__device__ __align__(16) float g_sums[NG * F];
__device__ float g_cnt[NG];
__device__ float g_dinv[NN];
__device__ float g_invdeg[NN];
__device__ int   g_deg[NN];
__device__ int   g_rowstart[NN];
__device__ int   g_cursor[NN];
__device__ int   g_counter;
__device__ int   g_ssorted[NE];

__device__ __forceinline__ void red_add_v4(float* p, float4 v) {
    asm volatile("red.global.add.v4.f32 [%0], {%1, %2, %3, %4};"
                 :: "l"(p), "f"(v.x), "f"(v.y), "f"(v.z), "f"(v.w) : "memory");
}

// ---------------- prep kernels ----------------
__global__ void zero_kernel() {
    int i = blockIdx.x * blockDim.x + threadIdx.x;
    if (i < NG * F) g_sums[i] = 0.0f;
    if (i < NG) g_cnt[i] = 0.0f;
    if (i == 0) g_counter = 0;
}

__global__ void deg_kernel(const int* __restrict__ dst) {
    int e = blockIdx.x * blockDim.x + threadIdx.x;
    if (e < NE) atomicAdd(&g_deg[dst[e]], 1);
}

// Fused: dinv/invdeg/cnt + block-local scan + block-atomic region placement.
// Row regions are contiguous per 256-node block; block placement order is
// irrelevant for correctness (disjoint ranges) and intra-row reads stay
// sequential for the agg kernel.
__global__ void scan_fused_kernel(const int* __restrict__ batch) {
    __shared__ int s[2][256];
    __shared__ int blockoff;
    int tid = threadIdx.x;
    int i = blockIdx.x * 256 + tid;
    int v = (i < NN) ? g_deg[i] : 0;
    s[0][tid] = v;
    if (i < NN) {
        float d = (float)(v + 1);
        g_dinv[i] = rsqrtf(d);
        g_invdeg[i] = 1.0f / d;
        atomicAdd(&g_cnt[batch[i]], 1.0f);
    }
    __syncthreads();
    int cur = 0;
#pragma unroll
    for (int off = 1; off < 256; off <<= 1) {
        int val = s[cur][tid];
        if (tid >= off) val += s[cur][tid - off];
        s[cur ^ 1][tid] = val;
        cur ^= 1;
        __syncthreads();
    }
    if (tid == 0) blockoff = atomicAdd(&g_counter, s[cur][255]);
    __syncthreads();
    int excl = (tid == 0) ? 0 : s[cur][tid - 1];
    if (i < NN) {
        int rs = excl + blockoff;
        g_rowstart[i] = rs;
        g_cursor[i] = rs;
    }
}

__global__ void scatter_kernel(const int* __restrict__ src, const int* __restrict__ dst) {
    int e = blockIdx.x * blockDim.x + threadIdx.x;
    if (e < NE) {
        int d = dst[e];
        int pos = atomicAdd(&g_cursor[d], 1);
        g_ssorted[pos] = src[e];
    }
}

// ---------------- GEMM + self-loop init (4 rows x 16 cols/thread) ----
// in = (FIRST ? x : relu(g_agg + b_prev)); a = in @ W
// g_hh = half(a * dinv); g_agg = a * invdeg
// Block: 128 threads = 32 quads x 4 parts; 128 nodes/block.
template <bool FIRST>
__global__ __launch_bounds__(128) void gemm_kernel(const float* __restrict__ x,
                                                   const float* __restrict__ W,
                                                   const float* __restrict__ bprev) {
    __shared__ float4 Ws[F * 16];
    int tid = threadIdx.x;
    const float4* W4 = (const float4*)W;
#pragma unroll
    for (int i = tid; i < F * 16; i += 128) Ws[i] = W4[i];
    __syncthreads();

    int part = tid & 3;
    int quad = tid >> 2;
    int base = blockIdx.x * 128 + quad * 4;

    const float4* in4 = FIRST ? (const float4*)x : (const float4*)g_agg;
    const float4* b4 = (const float4*)bprev;

    float4 acc[4][4];
#pragma unroll
    for (int r = 0; r < 4; ++r)
#pragma unroll
        for (int j = 0; j < 4; ++j) acc[r][j] = make_float4(0.f, 0.f, 0.f, 0.f);

#pragma unroll
    for (int k4 = 0; k4 < 16; ++k4) {
        float4 bv;
        if (!FIRST) bv = b4[k4];
        float xs[4][4];
#pragma unroll
        for (int r = 0; r < 4; ++r) {
            int node = base + r;
            float4 xv = make_float4(0.f, 0.f, 0.f, 0.f);
            if (node < NN) {
                xv = in4[(size_t)node * 16 + k4];
                if (!FIRST) {
                    xv.x = fmaxf(xv.x + bv.x, 0.f);
                    xv.y = fmaxf(xv.y + bv.y, 0.f);
                    xv.z = fmaxf(xv.z + bv.z, 0.f);
                    xv.w = fmaxf(xv.w + bv.w, 0.f);
                }
            }
            xs[r][0] = xv.x; xs[r][1] = xv.y; xs[r][2] = xv.z; xs[r][3] = xv.w;
        }
#pragma unroll
        for (int kk = 0; kk < 4; ++kk) {
            const float4* wrow = &Ws[(k4 * 4 + kk) * 16 + part * 4];
            float4 w0 = wrow[0], w1 = wrow[1], w2 = wrow[2], w3 = wrow[3];
#pragma unroll
            for (int r = 0; r < 4; ++r) {
                float v = xs[r][kk];
                acc[r][0].x = fmaf(v, w0.x, acc[r][0].x);
                acc[r][0].y = fmaf(v, w0.y, acc[r][0].y);
                acc[r][0].z = fmaf(v, w0.z, acc[r][0].z);
                acc[r][0].w = fmaf(v, w0.w, acc[r][0].w);
                acc[r][1].x = fmaf(v, w1.x, acc[r][1].x);
                acc[r][1].y = fmaf(v, w1.y, acc[r][1].y);
                acc[r][1].z = fmaf(v, w1.z, acc[r][1].z);
                acc[r][1].w = fmaf(v, w1.w, acc[r][1].w);
                acc[r][2].x = fmaf(v, w2.x, acc[r][2].x);
                acc[r][2].y = fmaf(v, w2.y, acc[r][2].y);
                acc[r][2].z = fmaf(v, w2.z, acc[r][2].z);
                acc[r][2].w = fmaf(v, w2.w, acc[r][2].w);
                acc[r][3].x = fmaf(v, w3.x, acc[r][3].x);
                acc[r][3].y = fmaf(v, w3.y, acc[r][3].y);
                acc[r][3].z = fmaf(v, w3.z, acc[r][3].z);
                acc[r][3].w = fmaf(v, w3.w, acc[r][3].w);
            }
        }
    }

#pragma unroll
    for (int r = 0; r < 4; ++r) {
        int node = base + r;
        if (node >= NN) continue;
        float dv = g_dinv[node];
        float id = g_invdeg[node];
        __half2* hr = (__half2*)(g_hh + (size_t)node * F + part * 16);
        float4* ar = (float4*)(g_agg + (size_t)node * F) + part * 4;
#pragma unroll
        for (int j = 0; j < 4; ++j) {
            float4 a = acc[r][j];
            hr[j * 2 + 0] = __floats2half2_rn(a.x * dv, a.y * dv);
            hr[j * 2 + 1] = __floats2half2_rn(a.z * dv, a.w * dv);
            ar[j] = make_float4(a.x * id, a.y * id, a.z * id, a.w * id);
        }
    }
}

// ---------------- CSR aggregation: 8-lane group per dst, fp16 gather, MLP=4 ----
template <bool LAST>
__global__ __launch_bounds__(256) void agg_kernel(const int* __restrict__ batch,
                                                  const float* __restrict__ b3) {
    int t = blockIdx.x * blockDim.x + threadIdx.x;
    int d = t >> 3;
    int l = t & 7;            // 8 lanes x 8 features (16B) per lane
    if (d >= NN) return;
    int start = g_rowstart[d];
    int n = g_deg[d];
    const uint4* h4 = (const uint4*)g_hh;   // one uint4 = 8 halfs

    float acc[8];
#pragma unroll
    for (int j = 0; j < 8; ++j) acc[j] = 0.f;

    int i = 0;
    for (; i + 4 <= n; i += 4) {
        int s0 = g_ssorted[start + i];
        int s1 = g_ssorted[start + i + 1];
        int s2 = g_ssorted[start + i + 2];
        int s3 = g_ssorted[start + i + 3];
        uint4 r0 = h4[(size_t)s0 * 8 + l];
        uint4 r1 = h4[(size_t)s1 * 8 + l];
        uint4 r2 = h4[(size_t)s2 * 8 + l];
        uint4 r3 = h4[(size_t)s3 * 8 + l];
        const __half2* p0 = (const __half2*)&r0;
        const __half2* p1 = (const __half2*)&r1;
        const __half2* p2 = (const __half2*)&r2;
        const __half2* p3 = (const __half2*)&r3;
#pragma unroll
        for (int j = 0; j < 4; ++j) {
            float2 f0 = __half22float2(p0[j]);
            float2 f1 = __half22float2(p1[j]);
            float2 f2 = __half22float2(p2[j]);
            float2 f3 = __half22float2(p3[j]);
            acc[j * 2 + 0] += (f0.x + f1.x) + (f2.x + f3.x);
            acc[j * 2 + 1] += (f0.y + f1.y) + (f2.y + f3.y);
        }
    }
    for (; i < n; ++i) {
        int s0 = g_ssorted[start + i];
        uint4 r0 = h4[(size_t)s0 * 8 + l];
        const __half2* p0 = (const __half2*)&r0;
#pragma unroll
        for (int j = 0; j < 4; ++j) {
            float2 f0 = __half22float2(p0[j]);
            acc[j * 2 + 0] += f0.x;
            acc[j * 2 + 1] += f0.y;
        }
    }

    float dd = g_dinv[d];
    float4* ar = (float4*)(g_agg + (size_t)d * F + l * 8);
    float4 s0v = ar[0];
    float4 s1v = ar[1];
    float4 o0 = make_float4(fmaf(acc[0], dd, s0v.x), fmaf(acc[1], dd, s0v.y),
                            fmaf(acc[2], dd, s0v.z), fmaf(acc[3], dd, s0v.w));
    float4 o1 = make_float4(fmaf(acc[4], dd, s1v.x), fmaf(acc[5], dd, s1v.y),
                            fmaf(acc[6], dd, s1v.z), fmaf(acc[7], dd, s1v.w));
    if (!LAST) {
        ar[0] = o0;
        ar[1] = o1;
    } else {
        float4 b0 = ((const float4*)b3)[l * 2 + 0];
        float4 b1 = ((const float4*)b3)[l * 2 + 1];
        o0.x = fmaxf(o0.x + b0.x, 0.f); o0.y = fmaxf(o0.y + b0.y, 0.f);
        o0.z = fmaxf(o0.z + b0.z, 0.f); o0.w = fmaxf(o0.w + b0.w, 0.f);
        o1.x = fmaxf(o1.x + b1.x, 0.f); o1.y = fmaxf(o1.y + b1.y, 0.f);
        o1.z = fmaxf(o1.z + b1.z, 0.f); o1.w = fmaxf(o1.w + b1.w, 0.f);
        int g = batch[d];
        red_add_v4(g_sums + (size_t)g * F + l * 8, o0);
        red_add_v4(g_sums + (size_t)g * F + l * 8 + 4, o1);
    }
}

// out[g] = (sums[g] . Wl) / max(cnt,1) + bl
__global__ void final_kernel(const float* __restrict__ Wl, const float* __restrict__ bl,
                             float* __restrict__ out) {
    int g = threadIdx.x;
    float c = fmaxf(g_cnt[g], 1.0f);
    float acc = 0.f;
#pragma unroll
    for (int f = 0; f < F; ++f) acc = fmaf(g_sums[g * F + f], Wl[f], acc);
    out[g] = acc / c + bl[0];
}

// ---------------- launch ----------------
extern "C" void kernel_launch(void* const* d_in, const int* in_sizes, int n_in,
                              void* d_out, int out_size) {
    const float* x   = (const float*)d_in[0];
    const int* src   = (const int*)d_in[1];
    const int* dst   = (const int*)d_in[2];
    const int* batch = (const int*)d_in[3];
    const float* W1 = (const float*)d_in[4];
    const float* b1 = (const float*)d_in[5];
    const float* W2 = (const float*)d_in[6];
    const float* b2 = (const float*)d_in[7];
    const float* W3 = (const float*)d_in[8];
    const float* b3 = (const float*)d_in[9];
    const float* Wl = (const float*)d_in[10];
    const float* bl = (const float*)d_in[11];
    float* out = (float*)d_out;

    const int NB_NODE = (NN + 255) / 256;        // 196
    const int NB_EDGE = (NE + 255) / 256;        // 3125
    const int NB_GEMM = (NN + 127) / 128;        // 391
    const int NB_AGG  = (NN * 8 + 255) / 256;    // 1563
    const int NB_ZERO = (NG * F + 255) / 256;    // 64

    // zero g_deg via async memset (graph-capturable, no alloc)
    void* deg_ptr = nullptr;
    cudaGetSymbolAddress(&deg_ptr, g_deg);
    cudaMemsetAsync(deg_ptr, 0, NN * sizeof(int));

    zero_kernel<<<NB_ZERO, 256>>>();
    deg_kernel<<<NB_EDGE, 256>>>(dst);
    scan_fused_kernel<<<NB_NODE, 256>>>(batch);
    scatter_kernel<<<NB_EDGE, 256>>>(src, dst);

    // layer 1
    gemm_kernel<true><<<NB_GEMM, 128>>>(x, W1, nullptr);
    agg_kernel<false><<<NB_AGG, 256>>>(batch, b3);
    // layer 2
    gemm_kernel<false><<<NB_GEMM, 128>>>(nullptr, W2, b1);
    agg_kernel<false><<<NB_AGG, 256>>>(batch, b3);
    // layer 3 (+ fused pool)
    gemm_kernel<false><<<NB_GEMM, 128>>>(nullptr, W3, b2);
    agg_kernel<true><<<NB_AGG, 256>>>(batch, b3);

    final_kernel<<<1, 256>>>(Wl, bl, out);
}